// round 7
// baseline (speedup 1.0000x reference)
#include <cuda_runtime.h>
#include <cstdint>

#define NB   160                 // bins per unit length
#define NBX  161                 // x in [0,1]: bin = floor(x*NB), clamp 160
#define NBY  240                 // pers in [-0.5,1.0): bin = floor((p+0.5)*NB)
#define NBINS (NBX * NBY)        // 38640
#define HH 50
#define WW 50
#define HCTA 592                 // 4 CTAs/SM * 148 SMs, single wave
#define HTPB 512

__device__ float g_hist[NBINS];          // zero-initialized; restored by k_tail
__device__ float g_image[HH * WW];
__device__ float g_rowmax[HH];
__device__ unsigned int g_done = 0;      // restored by k_tail

__device__ __forceinline__ float fast_exp2(float x) {
    float r; asm("ex2.approx.ftz.f32 %0, %1;" : "=f"(r) : "f"(x)); return r;
}

// ---------- kernel 1: nearest-neighbor splat, 1 global red.add per point ----------
__device__ __forceinline__ void splat(float x, float y) {
    float w = y - x;
    float t = fmaf(w, (float)NB, 0.5f * (float)NB);     // (w+0.5)*NB
    if (t >= 0.0f) {
        int by = min((int)t, NBY - 1);
        int bx = min((int)(x * (float)NB), NBX - 1);
        atomicAdd(&g_hist[by * NBX + bx], w);
    }
}
__global__ void __launch_bounds__(HTPB) k_hist(const float2* __restrict__ pairs, int npts)
{
    const int n4 = npts >> 1;
    const float4* p4 = (const float4*)pairs;
    const int stride = gridDim.x * HTPB;
    for (int j = blockIdx.x * HTPB + threadIdx.x; j < n4; j += stride) {
        float4 q = p4[j];
        splat(q.x, q.y);
        splat(q.z, q.w);
    }
    if ((npts & 1) && blockIdx.x == 0 && threadIdx.x == 0) {
        float2 p = pairs[npts - 1];
        splat(p.x, p.y);
    }
}

// ---------- kernel 2: fused tail — row CTAs + elected last CTA finishes ----------
__global__ void __launch_bounds__(256) k_tail(
    const float* __restrict__ sigp,
    const float* __restrict__ gridx,
    const float* __restrict__ gridy,
    float* __restrict__ out)
{
    __shared__ float gyv[NBY];
    __shared__ float sM[NBX];
    __shared__ float sred[4][64];
    __shared__ float wmax[2];
    __shared__ unsigned int s_last;
    __shared__ float s_den;

    const int h = blockIdx.x;
    const int tid = threadIdx.x;
    const float sig = *sigp;
    const float c2 = -1.4426950408889634f / (2.0f * sig * sig);

    // gyv[by] = exp(c2*(gy[h]-yc)^2)
    if (tid < NBY) {
        float yc = ((float)tid + 0.5f) * (1.0f / NB) - 0.5f;
        float d = gridy[h] - yc;
        gyv[tid] = fast_exp2(c2 * d * d);
    }
    __syncthreads();

    // sM[bx] = sum_by gyv[by] * hist[by][bx]   (coalesced L2 loads)
    if (tid < NBX) {
        float a0 = 0.f, a1 = 0.f, a2 = 0.f, a3 = 0.f;
        #pragma unroll 4
        for (int by = 0; by < NBY; by += 4) {
            a0 = fmaf(g_hist[(by    ) * NBX + tid], gyv[by    ], a0);
            a1 = fmaf(g_hist[(by + 1) * NBX + tid], gyv[by + 1], a1);
            a2 = fmaf(g_hist[(by + 2) * NBX + tid], gyv[by + 2], a2);
            a3 = fmaf(g_hist[(by + 3) * NBX + tid], gyv[by + 3], a3);
        }
        sM[tid] = (a0 + a1) + (a2 + a3);
    }
    __syncthreads();

    // img[h][w] = sum_bx sM[bx] * exp(c2*(gx[w]-xc)^2)   (4-seg reduction)
    const int seg = tid >> 6;
    const int w = tid & 63;
    float acc = 0.0f;
    if (w < WW) {
        const float gw = gridx[w];
        for (int bx = seg; bx < NBX; bx += 4) {
            float xc = ((float)bx + 0.5f) * (1.0f / NB);
            float d = gw - xc;
            acc = fmaf(sM[bx], fast_exp2(c2 * d * d), acc);
        }
    }
    sred[seg][w] = acc;
    __syncthreads();

    if (seg == 0) {
        float v = (sred[0][w] + sred[1][w]) + (sred[2][w] + sred[3][w]);
        float m = -3.0e38f;
        if (w < WW) { g_image[h * WW + w] = v; m = v; }
        #pragma unroll
        for (int off = 16; off > 0; off >>= 1)
            m = fmaxf(m, __shfl_xor_sync(0xFFFFFFFFu, m, off));
        if ((tid & 31) == 0) wmax[tid >> 5] = m;
    }
    __syncthreads();
    if (tid == 0) g_rowmax[h] = fmaxf(wmax[0], wmax[1]);

    // --- election: last CTA to finish does the epilogue ---
    __threadfence();
    __syncthreads();
    if (tid == 0) s_last = (atomicAdd(&g_done, 1u) == HH - 1u);
    __syncthreads();
    if (!s_last) return;
    __threadfence();   // acquire: all CTAs' g_image/g_rowmax now visible

    // global max of 50 row maxes
    {
        float m = (tid < HH) ? g_rowmax[tid] : -3.0e38f;
        if (tid < 64) {
            #pragma unroll
            for (int off = 16; off > 0; off >>= 1)
                m = fmaxf(m, __shfl_xor_sync(0xFFFFFFFFu, m, off));
            if ((tid & 31) == 0) wmax[tid >> 5] = m;
        }
        __syncthreads();
        if (tid == 0) s_den = fmaxf(wmax[0], wmax[1]) + 1e-8f;
        __syncthreads();
    }
    const float den = s_den;
    for (int i = tid; i < HH * WW; i += 256) out[i] = g_image[i] / den;

    // restore state for next graph replay (all tail CTAs have consumed hist)
    float4* hz = (float4*)g_hist;
    for (int i = tid; i < NBINS / 4; i += 256) hz[i] = make_float4(0.f, 0.f, 0.f, 0.f);
    // NBINS = 38640 = 4*9660, divisible — no remainder
    if (tid == 0) g_done = 0;
}

extern "C" void kernel_launch(void* const* d_in, const int* in_sizes, int n_in,
                              void* d_out, int out_size) {
    const float2* pairs = (const float2*)d_in[0];
    const float*  sigma = (const float*)d_in[1];
    const float*  gx    = (const float*)d_in[2];
    const float*  gy    = (const float*)d_in[3];
    float* out = (float*)d_out;

    int npts = in_sizes[0] / 2;

    k_hist<<<HCTA, HTPB>>>(pairs, npts);
    k_tail<<<HH, 256>>>(sigma, gx, gy, out);
}

// round 8
// speedup vs baseline: 1.1225x; 1.1225x over previous
#include <cuda_runtime.h>
#include <cstdint>

#define NB   160                 // bins per unit length
#define NBX  161                 // x in [0,1]: bin = floor(x*NB), clamp 160
#define NBY  240                 // pers in [-0.5,1.0): bin = floor((p+0.5)*NB)
#define NBINS (NBX * NBY)        // 38640
#define HH 50
#define WW 50
#define GRID 148
#define TPB  1024
#define SEGY 6                   // by-segments for sM (6*161 = 966 threads)
#define BYSEG (NBY / SEGY)       // 40

__device__ float g_hist[NBINS];          // zero-init; restored each run
__device__ float g_image[HH * WW];
__device__ float g_rowmax[HH];
__device__ unsigned int g_done1 = 0;     // splat-phase counter (restored)
__device__ unsigned int g_done2 = 0;     // tail-phase counter  (restored)

__device__ __forceinline__ float fast_exp2(float x) {
    float r; asm("ex2.approx.ftz.f32 %0, %1;" : "=f"(r) : "f"(x)); return r;
}

__device__ __forceinline__ void splat(float x, float y) {
    float w = y - x;
    float t = fmaf(w, (float)NB, 0.5f * (float)NB);     // (w+0.5)*NB
    if (t >= 0.0f) {
        int by = min((int)t, NBY - 1);
        int bx = min((int)(x * (float)NB), NBX - 1);
        atomicAdd(&g_hist[by * NBX + bx], w);           // REDG (no return)
    }
}

__global__ void __launch_bounds__(TPB) k_all(
    const float2* __restrict__ pairs, int npts,
    const float* __restrict__ sigp,
    const float* __restrict__ gridx,
    const float* __restrict__ gridy,
    float* __restrict__ out)
{
    __shared__ float gyv[NBY];
    __shared__ float sMp[SEGY][NBX];
    __shared__ float sred[16][64];
    __shared__ float wmax[2];
    __shared__ float s_den;

    const int tid = threadIdx.x;

    // ---------------- phase 1: splat (all 148 CTAs) ----------------
    {
        const int n4 = npts >> 1;
        const float4* p4 = (const float4*)pairs;
        const int stride = GRID * TPB;
        for (int j = blockIdx.x * TPB + tid; j < n4; j += stride) {
            float4 q = p4[j];
            splat(q.x, q.y);
            splat(q.z, q.w);
        }
        if ((npts & 1) && blockIdx.x == 0 && tid == 0) {
            float2 p = pairs[npts - 1];
            splat(p.x, p.y);
        }
    }
    __threadfence();          // release: REDs ordered before the counter bump
    __syncthreads();
    if (tid == 0) atomicAdd(&g_done1, 1u);

    const int h = blockIdx.x;
    if (h >= HH) return;      // 98 CTAs exit, freeing SMs

    // ---------------- transition: wait for all splats ----------------
    if (tid == 0) {
        while (*(volatile unsigned int*)&g_done1 != GRID) __nanosleep(64);
    }
    __syncthreads();
    __threadfence();          // acquire: all REDs now visible

    const float sig = *sigp;
    const float c2 = -1.4426950408889634f / (2.0f * sig * sig);

    // gyv[by] = exp(c2*(gy[h]-yc)^2)
    if (tid < NBY) {
        float yc = ((float)tid + 0.5f) * (1.0f / NB) - 0.5f;
        float d = gridy[h] - yc;
        gyv[tid] = fast_exp2(c2 * d * d);
    }
    __syncthreads();

    // sM[bx] = sum_by gyv[by]*hist[by][bx] — 966 threads, 6 by-segments
    if (tid < SEGY * NBX) {
        const int seg = tid / NBX;
        const int bx  = tid - seg * NBX;
        const int by0 = seg * BYSEG;
        float a0 = 0.f, a1 = 0.f, a2 = 0.f, a3 = 0.f;
        #pragma unroll
        for (int k = 0; k < BYSEG; k += 4) {
            int by = by0 + k;
            a0 = fmaf(g_hist[(by    ) * NBX + bx], gyv[by    ], a0);
            a1 = fmaf(g_hist[(by + 1) * NBX + bx], gyv[by + 1], a1);
            a2 = fmaf(g_hist[(by + 2) * NBX + bx], gyv[by + 2], a2);
            a3 = fmaf(g_hist[(by + 3) * NBX + bx], gyv[by + 3], a3);
        }
        sMp[seg][bx] = (a0 + a1) + (a2 + a3);
    }
    __syncthreads();
    if (tid < NBX) {
        float s = sMp[0][tid];
        #pragma unroll
        for (int s2 = 1; s2 < SEGY; s2++) s += sMp[s2][tid];
        sMp[0][tid] = s;
    }
    __syncthreads();

    // img[h][w] = sum_bx sM[bx]*exp(c2*(gx[w]-xc)^2) — 16 segments x 64 lanes
    {
        const int seg = tid >> 6;       // 0..15
        const int w   = tid & 63;
        float acc = 0.0f;
        if (w < WW) {
            const float gw = gridx[w];
            for (int bx = seg; bx < NBX; bx += 16) {
                float xc = ((float)bx + 0.5f) * (1.0f / NB);
                float d = gw - xc;
                acc = fmaf(sMp[0][bx], fast_exp2(c2 * d * d), acc);
            }
        }
        sred[seg][w] = acc;
    }
    __syncthreads();

    unsigned int ticket = 0xFFFFFFFFu;
    if (tid < 64) {
        const int w = tid;
        float v = 0.0f;
        #pragma unroll
        for (int s2 = 0; s2 < 16; s2++) v += sred[s2][w];
        float m = -3.0e38f;
        if (w < WW) { g_image[h * WW + w] = v; m = v; }
        #pragma unroll
        for (int off = 16; off > 0; off >>= 1)
            m = fmaxf(m, __shfl_xor_sync(0xFFFFFFFFu, m, off));
        if ((tid & 31) == 0) wmax[tid >> 5] = m;
    }
    __syncthreads();
    if (tid == 0) {
        g_rowmax[h] = fmaxf(wmax[0], wmax[1]);
        __threadfence();                       // release row data
        ticket = atomicAdd(&g_done2, 1u);
        wmax[0] = (float)ticket;               // broadcast ticket via smem
    }
    __syncthreads();
    if ((unsigned int)__float2int_rn(wmax[0]) != HH - 1u) return;
    __threadfence();                           // acquire all rows

    // ---------------- epilogue (single surviving CTA) ----------------
    {
        float m = (tid < HH) ? g_rowmax[tid] : -3.0e38f;
        if (tid < 64) {
            #pragma unroll
            for (int off = 16; off > 0; off >>= 1)
                m = fmaxf(m, __shfl_xor_sync(0xFFFFFFFFu, m, off));
            if ((tid & 31) == 0) wmax[tid >> 5] = m;
        }
        __syncthreads();
        if (tid == 0) s_den = fmaxf(wmax[0], wmax[1]) + 1e-8f;
        __syncthreads();
        const float den = s_den;
        for (int i = tid; i < HH * WW; i += TPB) out[i] = g_image[i] / den;
    }
    // restore state for next graph replay
    {
        float4* hz = (float4*)g_hist;          // NBINS = 38640 = 4*9660
        for (int i = tid; i < NBINS / 4; i += TPB)
            hz[i] = make_float4(0.f, 0.f, 0.f, 0.f);
        if (tid == 0) { g_done1 = 0; g_done2 = 0; }
    }
}

extern "C" void kernel_launch(void* const* d_in, const int* in_sizes, int n_in,
                              void* d_out, int out_size) {
    const float2* pairs = (const float2*)d_in[0];
    const float*  sigma = (const float*)d_in[1];
    const float*  gx    = (const float*)d_in[2];
    const float*  gy    = (const float*)d_in[3];
    float* out = (float*)d_out;

    int npts = in_sizes[0] / 2;

    k_all<<<GRID, TPB>>>(pairs, npts, sigma, gx, gy, out);
}